// round 2
// baseline (speedup 1.0000x reference)
#include <cuda_runtime.h>
#include <cuda_fp16.h>
#include <cstdint>

#define N_NODES 100000
#define N_EDGES 3200000
#define F_IN    256
#define F_H     64

// ---------------- scratch (device globals: allocation-free) ----------------
__device__ __align__(16) __half g_Hs [(size_t)N_NODES * F_H];  // H = x@W (unscaled, fp16)
__device__ __align__(16) float  g_ACC[(size_t)N_NODES * F_H];  // aggregated, fp32
__device__ float g_dinv[N_NODES];
__device__ int   g_cnt [N_NODES];
__device__ int   g_rowptr[N_NODES + 1];
__device__ int   g_fill[N_NODES];
__device__ int   g_esrc[N_EDGES];
__device__ int   g_is64;

// ---------------- edge-index dtype sniffer ----------------
__global__ void detect_kernel(const int* __restrict__ ei32) {
    if (blockIdx.x == 0 && threadIdx.x == 0) {
        int ok64 = 1;
        #pragma unroll
        for (int i = 0; i < 8; ++i)
            if (ei32[2 * i + 1] != 0) ok64 = 0;
        g_is64 = ok64;
    }
}

__device__ __forceinline__ int load_idx(const void* ei, size_t pos, int is64) {
    if (is64) return (int)((const long long*)ei)[pos];
    return ((const int*)ei)[pos];
}

// ---------------- zero degree counters ----------------
__global__ void zero_cnt_kernel() {
    int n = blockIdx.x * blockDim.x + threadIdx.x;
    if (n < N_NODES) g_cnt[n] = 0;
}

// ---------------- degree count (dst side) ----------------
__global__ void count_kernel(const void* __restrict__ ei) {
    int e = blockIdx.x * blockDim.x + threadIdx.x;
    if (e >= N_EDGES) return;
    const int is64 = g_is64;
    int d = load_idx(ei, (size_t)N_EDGES + e, is64);
    atomicAdd(&g_cnt[d], 1);
}

// ---------------- dinv = rsqrt(deg + 1) ----------------
__global__ void dinv_kernel() {
    int n = blockIdx.x * blockDim.x + threadIdx.x;
    if (n < N_NODES) g_dinv[n] = rsqrtf((float)g_cnt[n] + 1.0f);
}

// ---------------- exclusive scan over g_cnt -> g_rowptr, g_fill ----------------
// Single block, 1024 threads, ~98 items each.
__global__ __launch_bounds__(1024) void scan_kernel() {
    __shared__ int ssum[1024];
    const int CH = (N_NODES + 1023) / 1024;
    int t = threadIdx.x;
    int base = t * CH;
    int s = 0;
    for (int i = 0; i < CH; ++i) {
        int idx = base + i;
        if (idx < N_NODES) s += g_cnt[idx];
    }
    ssum[t] = s;
    __syncthreads();
    // Hillis-Steele inclusive scan
    for (int off = 1; off < 1024; off <<= 1) {
        int v = (t >= off) ? ssum[t - off] : 0;
        __syncthreads();
        ssum[t] += v;
        __syncthreads();
    }
    int run = (t == 0) ? 0 : ssum[t - 1];
    for (int i = 0; i < CH; ++i) {
        int idx = base + i;
        if (idx < N_NODES) {
            g_rowptr[idx] = run;
            g_fill[idx]   = run;
            run += g_cnt[idx];
        }
    }
    if (t == 1023) g_rowptr[N_NODES] = ssum[1023];
}

// ---------------- CSR scatter: sort edge srcs into dst buckets ----------------
__global__ void csr_kernel(const void* __restrict__ ei) {
    int e = blockIdx.x * blockDim.x + threadIdx.x;
    if (e >= N_EDGES) return;
    const int is64 = g_is64;
    int s = load_idx(ei, (size_t)e, is64);
    int d = load_idx(ei, (size_t)N_EDGES + e, is64);
    int pos = atomicAdd(&g_fill[d], 1);
    g_esrc[pos] = s;
}

// ---------------- GEMM: Hs = half(x @ W_gcn)  (100000x256 @ 256x64) ----------------
#define G_TN  256
#define G_KK  16
#define G_LDN 260

__global__ __launch_bounds__(256) void gemm_kernel(
    const float* __restrict__ x, const float* __restrict__ W)
{
    __shared__ float xs[G_KK * G_LDN];
    __shared__ float ws[G_KK * 64];

    const int tid = threadIdx.x;
    const int nodeBase = blockIdx.x * G_TN;
    const int tc = tid & 7;
    const int tn = tid >> 3;
    const int lk = tid & 15;
    const int lnb = tid >> 4;

    float acc[8][8];
    #pragma unroll
    for (int i = 0; i < 8; ++i)
        #pragma unroll
        for (int j = 0; j < 8; ++j) acc[i][j] = 0.0f;

    for (int kk = 0; kk < F_IN; kk += G_KK) {
        #pragma unroll
        for (int p = 0; p < G_TN / 16; ++p) {
            int n = lnb + p * 16;
            int node = nodeBase + n;
            float v = 0.0f;
            if (node < N_NODES) v = x[(size_t)node * F_IN + kk + lk];
            xs[lk * G_LDN + n] = v;
        }
        #pragma unroll
        for (int p = 0; p < 4; ++p) {
            int idx = tid + p * 256;
            int k = idx >> 6, c = idx & 63;
            ws[idx] = W[(size_t)(kk + k) * 64 + c];
        }
        __syncthreads();

        #pragma unroll
        for (int k = 0; k < G_KK; ++k) {
            float4 a0 = *(const float4*)&xs[k * G_LDN + tn * 8];
            float4 a1 = *(const float4*)&xs[k * G_LDN + tn * 8 + 4];
            float4 b0 = *(const float4*)&ws[k * 64 + tc * 8];
            float4 b1 = *(const float4*)&ws[k * 64 + tc * 8 + 4];
            float av[8] = {a0.x, a0.y, a0.z, a0.w, a1.x, a1.y, a1.z, a1.w};
            float bv[8] = {b0.x, b0.y, b0.z, b0.w, b1.x, b1.y, b1.z, b1.w};
            #pragma unroll
            for (int i = 0; i < 8; ++i)
                #pragma unroll
                for (int j = 0; j < 8; ++j)
                    acc[i][j] += av[i] * bv[j];
        }
        __syncthreads();
    }

    #pragma unroll
    for (int i = 0; i < 8; ++i) {
        int node = nodeBase + tn * 8 + i;
        if (node < N_NODES) {
            __half2 p0 = __floats2half2_rn(acc[i][0], acc[i][1]);
            __half2 p1 = __floats2half2_rn(acc[i][2], acc[i][3]);
            __half2 p2 = __floats2half2_rn(acc[i][4], acc[i][5]);
            __half2 p3 = __floats2half2_rn(acc[i][6], acc[i][7]);
            uint4 u;
            u.x = *(uint32_t*)&p0; u.y = *(uint32_t*)&p1;
            u.z = *(uint32_t*)&p2; u.w = *(uint32_t*)&p3;
            *(uint4*)&g_Hs[(size_t)node * F_H + tc * 8] = u;
        }
    }
}

// ---------------- aggregate: warp per node, CSR gather, fp32 accumulate ----------------
// out[d] = dinv[d] * ( dinv[d]*H[d] + sum_{e: dst=d} dinv[src]*H[src] )
__global__ __launch_bounds__(256) void aggregate_kernel() {
    int w = blockIdx.x * 8 + (threadIdx.x >> 5);
    if (w >= N_NODES) return;
    int lane = threadIdx.x & 31;

    const __half2* __restrict__ H2 = (const __half2*)g_Hs;
    float dv = g_dinv[w];

    float2 acc;
    {
        float2 v = __half22float2(H2[(size_t)w * 32 + lane]);
        acc.x = v.x * dv;
        acc.y = v.y * dv;
    }

    int beg = g_rowptr[w], end = g_rowptr[w + 1];
    int i = beg;
    for (; i + 4 <= end; i += 4) {
        int s0 = g_esrc[i + 0], s1 = g_esrc[i + 1];
        int s2 = g_esrc[i + 2], s3 = g_esrc[i + 3];
        float d0 = g_dinv[s0], d1 = g_dinv[s1];
        float d2 = g_dinv[s2], d3 = g_dinv[s3];
        float2 v0 = __half22float2(H2[(size_t)s0 * 32 + lane]);
        float2 v1 = __half22float2(H2[(size_t)s1 * 32 + lane]);
        float2 v2 = __half22float2(H2[(size_t)s2 * 32 + lane]);
        float2 v3 = __half22float2(H2[(size_t)s3 * 32 + lane]);
        acc.x = fmaf(v0.x, d0, acc.x); acc.y = fmaf(v0.y, d0, acc.y);
        acc.x = fmaf(v1.x, d1, acc.x); acc.y = fmaf(v1.y, d1, acc.y);
        acc.x = fmaf(v2.x, d2, acc.x); acc.y = fmaf(v2.y, d2, acc.y);
        acc.x = fmaf(v3.x, d3, acc.x); acc.y = fmaf(v3.y, d3, acc.y);
    }
    for (; i < end; ++i) {
        int s = g_esrc[i];
        float ds = g_dinv[s];
        float2 v = __half22float2(H2[(size_t)s * 32 + lane]);
        acc.x = fmaf(v.x, ds, acc.x);
        acc.y = fmaf(v.y, ds, acc.y);
    }

    acc.x *= dv;
    acc.y *= dv;
    ((float2*)g_ACC)[(size_t)w * 32 + lane] = acc;
}

// ---------------- fused ReLU + MLP 64->32->16->10 ----------------
__global__ __launch_bounds__(128) void mlp_kernel(
    const float* __restrict__ b_gcn,
    const float* __restrict__ W1, const float* __restrict__ b1,
    const float* __restrict__ W2, const float* __restrict__ b2,
    const float* __restrict__ W3, const float* __restrict__ b3,
    float* __restrict__ out)
{
    __shared__ float sW1[64 * 32];
    __shared__ float sW2[32 * 16];
    __shared__ float sW3[16 * 10];
    __shared__ float sbg[64], sb1[32], sb2[16], sb3[10];

    const int tid = threadIdx.x;
    for (int i = tid; i < 64 * 32; i += 128) sW1[i] = W1[i];
    for (int i = tid; i < 32 * 16; i += 128) sW2[i] = W2[i];
    for (int i = tid; i < 16 * 10; i += 128) sW3[i] = W3[i];
    if (tid < 64) sbg[tid] = b_gcn[tid];
    if (tid < 32) sb1[tid] = b1[tid];
    if (tid < 16) sb2[tid] = b2[tid];
    if (tid < 10) sb3[tid] = b3[tid];
    __syncthreads();

    int node = blockIdx.x * 128 + tid;
    if (node >= N_NODES) return;

    float in[64];
    const float4* A4 = (const float4*)g_ACC;
    #pragma unroll
    for (int q = 0; q < 16; ++q) {
        float4 v = A4[(size_t)node * 16 + q];
        in[4 * q + 0] = fmaxf(v.x + sbg[4 * q + 0], 0.0f);
        in[4 * q + 1] = fmaxf(v.y + sbg[4 * q + 1], 0.0f);
        in[4 * q + 2] = fmaxf(v.z + sbg[4 * q + 2], 0.0f);
        in[4 * q + 3] = fmaxf(v.w + sbg[4 * q + 3], 0.0f);
    }

    float h1[32];
    #pragma unroll
    for (int j = 0; j < 32; ++j) h1[j] = sb1[j];
    #pragma unroll
    for (int k = 0; k < 64; ++k) {
        float a = in[k];
        #pragma unroll
        for (int j = 0; j < 32; ++j) h1[j] += a * sW1[k * 32 + j];
    }
    #pragma unroll
    for (int j = 0; j < 32; ++j) h1[j] = fmaxf(h1[j], 0.0f);

    float h2[16];
    #pragma unroll
    for (int j = 0; j < 16; ++j) h2[j] = sb2[j];
    #pragma unroll
    for (int k = 0; k < 32; ++k) {
        float a = h1[k];
        #pragma unroll
        for (int j = 0; j < 16; ++j) h2[j] += a * sW2[k * 16 + j];
    }
    #pragma unroll
    for (int j = 0; j < 16; ++j) h2[j] = fmaxf(h2[j], 0.0f);

    float o[10];
    #pragma unroll
    for (int j = 0; j < 10; ++j) o[j] = sb3[j];
    #pragma unroll
    for (int k = 0; k < 16; ++k) {
        float a = h2[k];
        #pragma unroll
        for (int j = 0; j < 10; ++j) o[j] += a * sW3[k * 10 + j];
    }
    #pragma unroll
    for (int j = 0; j < 10; ++j) out[(size_t)node * 10 + j] = o[j];
}

// ---------------- launcher ----------------
extern "C" void kernel_launch(void* const* d_in, const int* in_sizes, int n_in,
                              void* d_out, int out_size)
{
    const float* x     = (const float*)d_in[0];
    const void*  ei    = d_in[1];
    const float* W_gcn = (const float*)d_in[2];
    const float* b_gcn = (const float*)d_in[3];
    const float* W1    = (const float*)d_in[4];
    const float* b1    = (const float*)d_in[5];
    const float* W2    = (const float*)d_in[6];
    const float* b2    = (const float*)d_in[7];
    const float* W3    = (const float*)d_in[8];
    const float* b3    = (const float*)d_in[9];
    float* out = (float*)d_out;

    detect_kernel<<<1, 32>>>((const int*)ei);
    zero_cnt_kernel<<<(N_NODES + 255) / 256, 256>>>();
    count_kernel<<<(N_EDGES + 255) / 256, 256>>>(ei);
    dinv_kernel<<<(N_NODES + 255) / 256, 256>>>();
    scan_kernel<<<1, 1024>>>();
    csr_kernel<<<(N_EDGES + 255) / 256, 256>>>(ei);
    gemm_kernel<<<(N_NODES + G_TN - 1) / G_TN, 256>>>(x, W_gcn);
    aggregate_kernel<<<(N_NODES + 7) / 8, 256>>>();
    mlp_kernel<<<(N_NODES + 127) / 128, 128>>>(b_gcn, W1, b1, W2, b2, W3, b3, out);
}

// round 3
// speedup vs baseline: 1.5960x; 1.5960x over previous
#include <cuda_runtime.h>
#include <cuda_fp16.h>
#include <cstdint>

#define N_NODES 100000
#define N_EDGES 3200000
#define F_IN    256
#define F_H     64
#define NB      391   // ceil(N_NODES/256)

// ---------------- scratch (device globals: allocation-free) ----------------
__device__ __align__(16) __half g_Hs [(size_t)N_NODES * F_H];
__device__ __align__(16) float  g_ACC[(size_t)N_NODES * F_H];
__device__ float g_dinv[N_NODES];
__device__ int   g_cnt [N_NODES];
__device__ int   g_bsum[NB];
__device__ int   g_boff[NB];
__device__ int   g_rowptr[N_NODES + 1];
__device__ int   g_fill[N_NODES];
__device__ int   g_esrc[N_EDGES];
__device__ int   g_is64;

// ---------------- edge-index dtype sniffer ----------------
__global__ void detect_kernel(const int* __restrict__ ei32) {
    if (blockIdx.x == 0 && threadIdx.x == 0) {
        int ok64 = 1;
        #pragma unroll
        for (int i = 0; i < 8; ++i)
            if (ei32[2 * i + 1] != 0) ok64 = 0;
        g_is64 = ok64;
    }
}

__device__ __forceinline__ int load_idx(const void* ei, size_t pos, int is64) {
    if (is64) return (int)((const long long*)ei)[pos];
    return ((const int*)ei)[pos];
}

// ---------------- zero degree counters ----------------
__global__ void zero_cnt_kernel() {
    int n = blockIdx.x * blockDim.x + threadIdx.x;
    if (n < N_NODES) g_cnt[n] = 0;
}

// ---------------- degree count (dst side) ----------------
__global__ void count_kernel(const void* __restrict__ ei) {
    int e = blockIdx.x * blockDim.x + threadIdx.x;
    if (e >= N_EDGES) return;
    const int is64 = g_is64;
    int d = load_idx(ei, (size_t)N_EDGES + e, is64);
    atomicAdd(&g_cnt[d], 1);
}

// ---------------- scan phase 1: block sums + dinv ----------------
__global__ __launch_bounds__(256) void bsum_kernel() {
    __shared__ int red[256];
    int t = threadIdx.x;
    int idx = blockIdx.x * 256 + t;
    int c = (idx < N_NODES) ? g_cnt[idx] : 0;
    if (idx < N_NODES) g_dinv[idx] = rsqrtf((float)c + 1.0f);
    red[t] = c;
    __syncthreads();
    #pragma unroll
    for (int off = 128; off; off >>= 1) {
        if (t < off) red[t] += red[t + off];
        __syncthreads();
    }
    if (t == 0) g_bsum[blockIdx.x] = red[0];
}

// ---------------- scan phase 2: scan 391 block sums (1 block) ----------------
__global__ __launch_bounds__(512) void bscan_kernel() {
    __shared__ int s[512];
    int t = threadIdx.x;
    int v = (t < NB) ? g_bsum[t] : 0;
    s[t] = v;
    __syncthreads();
    #pragma unroll
    for (int off = 1; off < 512; off <<= 1) {
        int u = (t >= off) ? s[t - off] : 0;
        __syncthreads();
        s[t] += u;
        __syncthreads();
    }
    if (t < NB) g_boff[t] = s[t] - v;   // exclusive
}

// ---------------- scan phase 3: per-block exclusive scan -> rowptr ----------------
__global__ __launch_bounds__(256) void rowptr_kernel() {
    __shared__ int s[256];
    int t = threadIdx.x;
    int idx = blockIdx.x * 256 + t;
    int c = (idx < N_NODES) ? g_cnt[idx] : 0;
    s[t] = c;
    __syncthreads();
    #pragma unroll
    for (int off = 1; off < 256; off <<= 1) {
        int u = (t >= off) ? s[t - off] : 0;
        __syncthreads();
        s[t] += u;
        __syncthreads();
    }
    int ex = g_boff[blockIdx.x] + s[t] - c;
    if (idx < N_NODES) {
        g_rowptr[idx] = ex;
        g_fill[idx]   = ex;
        if (idx == N_NODES - 1) g_rowptr[N_NODES] = ex + c;
    }
}

// ---------------- CSR scatter: sort edge srcs into dst buckets ----------------
__global__ void csr_kernel(const void* __restrict__ ei) {
    int e = blockIdx.x * blockDim.x + threadIdx.x;
    if (e >= N_EDGES) return;
    const int is64 = g_is64;
    int s = load_idx(ei, (size_t)e, is64);
    int d = load_idx(ei, (size_t)N_EDGES + e, is64);
    int pos = atomicAdd(&g_fill[d], 1);
    g_esrc[pos] = s;
}

// ---------------- GEMM: Hs = half(x @ W_gcn)  (100000x256 @ 256x64) ----------------
#define G_TN  256
#define G_KK  16
#define G_LDN 260

__global__ __launch_bounds__(256) void gemm_kernel(
    const float* __restrict__ x, const float* __restrict__ W)
{
    __shared__ float xs[G_KK * G_LDN];
    __shared__ float ws[G_KK * 64];

    const int tid = threadIdx.x;
    const int nodeBase = blockIdx.x * G_TN;
    const int tc = tid & 7;
    const int tn = tid >> 3;
    const int lk = tid & 15;
    const int lnb = tid >> 4;

    float acc[8][8];
    #pragma unroll
    for (int i = 0; i < 8; ++i)
        #pragma unroll
        for (int j = 0; j < 8; ++j) acc[i][j] = 0.0f;

    for (int kk = 0; kk < F_IN; kk += G_KK) {
        #pragma unroll
        for (int p = 0; p < G_TN / 16; ++p) {
            int n = lnb + p * 16;
            int node = nodeBase + n;
            float v = 0.0f;
            if (node < N_NODES) v = x[(size_t)node * F_IN + kk + lk];
            xs[lk * G_LDN + n] = v;
        }
        #pragma unroll
        for (int p = 0; p < 4; ++p) {
            int idx = tid + p * 256;
            int k = idx >> 6, c = idx & 63;
            ws[idx] = W[(size_t)(kk + k) * 64 + c];
        }
        __syncthreads();

        #pragma unroll
        for (int k = 0; k < G_KK; ++k) {
            float4 a0 = *(const float4*)&xs[k * G_LDN + tn * 8];
            float4 a1 = *(const float4*)&xs[k * G_LDN + tn * 8 + 4];
            float4 b0 = *(const float4*)&ws[k * 64 + tc * 8];
            float4 b1 = *(const float4*)&ws[k * 64 + tc * 8 + 4];
            float av[8] = {a0.x, a0.y, a0.z, a0.w, a1.x, a1.y, a1.z, a1.w};
            float bv[8] = {b0.x, b0.y, b0.z, b0.w, b1.x, b1.y, b1.z, b1.w};
            #pragma unroll
            for (int i = 0; i < 8; ++i)
                #pragma unroll
                for (int j = 0; j < 8; ++j)
                    acc[i][j] += av[i] * bv[j];
        }
        __syncthreads();
    }

    #pragma unroll
    for (int i = 0; i < 8; ++i) {
        int node = nodeBase + tn * 8 + i;
        if (node < N_NODES) {
            __half2 p0 = __floats2half2_rn(acc[i][0], acc[i][1]);
            __half2 p1 = __floats2half2_rn(acc[i][2], acc[i][3]);
            __half2 p2 = __floats2half2_rn(acc[i][4], acc[i][5]);
            __half2 p3 = __floats2half2_rn(acc[i][6], acc[i][7]);
            uint4 u;
            u.x = *(uint32_t*)&p0; u.y = *(uint32_t*)&p1;
            u.z = *(uint32_t*)&p2; u.w = *(uint32_t*)&p3;
            *(uint4*)&g_Hs[(size_t)node * F_H + tc * 8] = u;
        }
    }
}

// ---------------- aggregate v2: warp/node, half-warp per neighbor row ----------------
// out[d] = dinv[d] * ( dinv[d]*H[d] + sum_{src->d} dinv[src]*H[src] )
__device__ __forceinline__ void acc_row(float4& acc, uint2 r, float ds) {
    float2 f0 = __half22float2(*(__half2*)&r.x);
    float2 f1 = __half22float2(*(__half2*)&r.y);
    acc.x = fmaf(f0.x, ds, acc.x);
    acc.y = fmaf(f0.y, ds, acc.y);
    acc.z = fmaf(f1.x, ds, acc.z);
    acc.w = fmaf(f1.y, ds, acc.w);
}

__global__ __launch_bounds__(256) void aggregate_kernel() {
    int w = blockIdx.x * 8 + (threadIdx.x >> 5);
    if (w >= N_NODES) return;
    const int lane = threadIdx.x & 31;
    const int half = lane >> 4;   // which neighbor stream
    const int q    = lane & 15;   // which uint2 (4 halves) of the row

    const uint2* __restrict__ H = (const uint2*)g_Hs;  // 16 uint2 per row
    const float dv = g_dinv[w];

    float4 acc = make_float4(0.f, 0.f, 0.f, 0.f);
    if (half == 0) {
        uint2 r = H[(size_t)w * 16 + q];
        acc_row(acc, r, dv);     // self-loop term (only stream 0)
    }

    const int beg = g_rowptr[w], end = g_rowptr[w + 1];
    int i = beg + half;
    // two neighbors per stream in flight
    for (; i + 2 < end; i += 4) {
        int s0 = g_esrc[i];
        int s1 = g_esrc[i + 2];
        float d0 = g_dinv[s0];
        float d1 = g_dinv[s1];
        uint2 r0 = H[(size_t)s0 * 16 + q];
        uint2 r1 = H[(size_t)s1 * 16 + q];
        acc_row(acc, r0, d0);
        acc_row(acc, r1, d1);
    }
    if (i < end) {
        int s = g_esrc[i];
        float ds = g_dinv[s];
        uint2 r = H[(size_t)s * 16 + q];
        acc_row(acc, r, ds);
    }

    // combine the two half-warp streams
    acc.x += __shfl_xor_sync(0xffffffffu, acc.x, 16);
    acc.y += __shfl_xor_sync(0xffffffffu, acc.y, 16);
    acc.z += __shfl_xor_sync(0xffffffffu, acc.z, 16);
    acc.w += __shfl_xor_sync(0xffffffffu, acc.w, 16);

    if (half == 0) {
        acc.x *= dv; acc.y *= dv; acc.z *= dv; acc.w *= dv;
        ((float4*)g_ACC)[(size_t)w * 16 + q] = acc;
    }
}

// ---------------- fused ReLU + MLP 64->32->16->10 ----------------
__global__ __launch_bounds__(128) void mlp_kernel(
    const float* __restrict__ b_gcn,
    const float* __restrict__ W1, const float* __restrict__ b1,
    const float* __restrict__ W2, const float* __restrict__ b2,
    const float* __restrict__ W3, const float* __restrict__ b3,
    float* __restrict__ out)
{
    __shared__ float sW1[64 * 32];
    __shared__ float sW2[32 * 16];
    __shared__ float sW3[16 * 10];
    __shared__ float sbg[64], sb1[32], sb2[16], sb3[10];

    const int tid = threadIdx.x;
    for (int i = tid; i < 64 * 32; i += 128) sW1[i] = W1[i];
    for (int i = tid; i < 32 * 16; i += 128) sW2[i] = W2[i];
    for (int i = tid; i < 16 * 10; i += 128) sW3[i] = W3[i];
    if (tid < 64) sbg[tid] = b_gcn[tid];
    if (tid < 32) sb1[tid] = b1[tid];
    if (tid < 16) sb2[tid] = b2[tid];
    if (tid < 10) sb3[tid] = b3[tid];
    __syncthreads();

    int node = blockIdx.x * 128 + tid;
    if (node >= N_NODES) return;

    float in[64];
    const float4* A4 = (const float4*)g_ACC;
    #pragma unroll
    for (int q = 0; q < 16; ++q) {
        float4 v = A4[(size_t)node * 16 + q];
        in[4 * q + 0] = fmaxf(v.x + sbg[4 * q + 0], 0.0f);
        in[4 * q + 1] = fmaxf(v.y + sbg[4 * q + 1], 0.0f);
        in[4 * q + 2] = fmaxf(v.z + sbg[4 * q + 2], 0.0f);
        in[4 * q + 3] = fmaxf(v.w + sbg[4 * q + 3], 0.0f);
    }

    float h1[32];
    #pragma unroll
    for (int j = 0; j < 32; ++j) h1[j] = sb1[j];
    #pragma unroll
    for (int k = 0; k < 64; ++k) {
        float a = in[k];
        #pragma unroll
        for (int j = 0; j < 32; ++j) h1[j] += a * sW1[k * 32 + j];
    }
    #pragma unroll
    for (int j = 0; j < 32; ++j) h1[j] = fmaxf(h1[j], 0.0f);

    float h2[16];
    #pragma unroll
    for (int j = 0; j < 16; ++j) h2[j] = sb2[j];
    #pragma unroll
    for (int k = 0; k < 32; ++k) {
        float a = h1[k];
        #pragma unroll
        for (int j = 0; j < 16; ++j) h2[j] += a * sW2[k * 16 + j];
    }
    #pragma unroll
    for (int j = 0; j < 16; ++j) h2[j] = fmaxf(h2[j], 0.0f);

    float o[10];
    #pragma unroll
    for (int j = 0; j < 10; ++j) o[j] = sb3[j];
    #pragma unroll
    for (int k = 0; k < 16; ++k) {
        float a = h2[k];
        #pragma unroll
        for (int j = 0; j < 10; ++j) o[j] += a * sW3[k * 10 + j];
    }
    #pragma unroll
    for (int j = 0; j < 10; ++j) out[(size_t)node * 10 + j] = o[j];
}

// ---------------- launcher ----------------
extern "C" void kernel_launch(void* const* d_in, const int* in_sizes, int n_in,
                              void* d_out, int out_size)
{
    const float* x     = (const float*)d_in[0];
    const void*  ei    = d_in[1];
    const float* W_gcn = (const float*)d_in[2];
    const float* b_gcn = (const float*)d_in[3];
    const float* W1    = (const float*)d_in[4];
    const float* b1    = (const float*)d_in[5];
    const float* W2    = (const float*)d_in[6];
    const float* b2    = (const float*)d_in[7];
    const float* W3    = (const float*)d_in[8];
    const float* b3    = (const float*)d_in[9];
    float* out = (float*)d_out;

    detect_kernel<<<1, 32>>>((const int*)ei);
    zero_cnt_kernel<<<NB, 256>>>();
    count_kernel<<<(N_EDGES + 255) / 256, 256>>>(ei);
    bsum_kernel<<<NB, 256>>>();
    bscan_kernel<<<1, 512>>>();
    rowptr_kernel<<<NB, 256>>>();
    csr_kernel<<<(N_EDGES + 255) / 256, 256>>>(ei);
    gemm_kernel<<<(N_NODES + G_TN - 1) / G_TN, 256>>>(x, W_gcn);
    aggregate_kernel<<<(N_NODES + 7) / 8, 256>>>();
    mlp_kernel<<<(N_NODES + 127) / 128, 128>>>(b_gcn, W1, b1, W2, b2, W3, b3, out);
}

// round 4
// speedup vs baseline: 2.1503x; 1.3473x over previous
#include <cuda_runtime.h>
#include <cuda_fp16.h>
#include <cstdint>

#define N_NODES 100000
#define N_EDGES 3200000
#define F_IN    256
#define F_H     64
#define NB      391   // ceil(N_NODES/256)

// ---------------- scratch (device globals: allocation-free) ----------------
__device__ __align__(16) __half g_Hs [(size_t)N_NODES * F_H];
__device__ __align__(16) float  g_ACC[(size_t)N_NODES * F_H];
__device__ float g_dinv[N_NODES];
__device__ int   g_cnt [N_NODES];
__device__ int   g_bsum[NB];
__device__ int   g_boff[NB];
__device__ int   g_rowptr[N_NODES + 1];
__device__ int   g_fill[N_NODES];
__device__ int   g_esrc[N_EDGES];
__device__ int   g_is64;

// ---------------- edge-index dtype sniffer ----------------
__global__ void detect_kernel(const int* __restrict__ ei32) {
    if (blockIdx.x == 0 && threadIdx.x == 0) {
        int ok64 = 1;
        #pragma unroll
        for (int i = 0; i < 8; ++i)
            if (ei32[2 * i + 1] != 0) ok64 = 0;
        g_is64 = ok64;
    }
}

__device__ __forceinline__ int load_idx(const void* ei, size_t pos, int is64) {
    if (is64) return (int)((const long long*)ei)[pos];
    return ((const int*)ei)[pos];
}

// ---------------- zero degree counters ----------------
__global__ void zero_cnt_kernel() {
    int n = blockIdx.x * blockDim.x + threadIdx.x;
    if (n < N_NODES) g_cnt[n] = 0;
}

// ---------------- degree count (dst side) ----------------
__global__ void count_kernel(const void* __restrict__ ei) {
    int e = blockIdx.x * blockDim.x + threadIdx.x;
    if (e >= N_EDGES) return;
    const int is64 = g_is64;
    int d = load_idx(ei, (size_t)N_EDGES + e, is64);
    atomicAdd(&g_cnt[d], 1);
}

// ---------------- scan phase 1: block sums + dinv ----------------
__global__ __launch_bounds__(256) void bsum_kernel() {
    __shared__ int red[256];
    int t = threadIdx.x;
    int idx = blockIdx.x * 256 + t;
    int c = (idx < N_NODES) ? g_cnt[idx] : 0;
    if (idx < N_NODES) g_dinv[idx] = rsqrtf((float)c + 1.0f);
    red[t] = c;
    __syncthreads();
    #pragma unroll
    for (int off = 128; off; off >>= 1) {
        if (t < off) red[t] += red[t + off];
        __syncthreads();
    }
    if (t == 0) g_bsum[blockIdx.x] = red[0];
}

// ---------------- scan phase 2: scan 391 block sums (1 block) ----------------
__global__ __launch_bounds__(512) void bscan_kernel() {
    __shared__ int s[512];
    int t = threadIdx.x;
    int v = (t < NB) ? g_bsum[t] : 0;
    s[t] = v;
    __syncthreads();
    #pragma unroll
    for (int off = 1; off < 512; off <<= 1) {
        int u = (t >= off) ? s[t - off] : 0;
        __syncthreads();
        s[t] += u;
        __syncthreads();
    }
    if (t < NB) g_boff[t] = s[t] - v;   // exclusive
}

// ---------------- scan phase 3: per-block exclusive scan -> rowptr ----------------
__global__ __launch_bounds__(256) void rowptr_kernel() {
    __shared__ int s[256];
    int t = threadIdx.x;
    int idx = blockIdx.x * 256 + t;
    int c = (idx < N_NODES) ? g_cnt[idx] : 0;
    s[t] = c;
    __syncthreads();
    #pragma unroll
    for (int off = 1; off < 256; off <<= 1) {
        int u = (t >= off) ? s[t - off] : 0;
        __syncthreads();
        s[t] += u;
        __syncthreads();
    }
    int ex = g_boff[blockIdx.x] + s[t] - c;
    if (idx < N_NODES) {
        g_rowptr[idx] = ex;
        g_fill[idx]   = ex;
        if (idx == N_NODES - 1) g_rowptr[N_NODES] = ex + c;
    }
}

// ---------------- CSR scatter: sort edge srcs into dst buckets ----------------
__global__ void csr_kernel(const void* __restrict__ ei) {
    int e = blockIdx.x * blockDim.x + threadIdx.x;
    if (e >= N_EDGES) return;
    const int is64 = g_is64;
    int s = load_idx(ei, (size_t)e, is64);
    int d = load_idx(ei, (size_t)N_EDGES + e, is64);
    int pos = atomicAdd(&g_fill[d], 1);
    g_esrc[pos] = s;
}

// ---------------- HMMA GEMM: Hs = half(x @ W_gcn) ----------------
// Block tile 128x64, K-tile 64, 8 warps (each warp: 16 rows x 64 cols).
#define GM_M   128
#define XS_LD  72
#define WS_LD  72

__global__ __launch_bounds__(256) void gemm_kernel(
    const float* __restrict__ x, const float* __restrict__ W)
{
    __shared__ __half xs [GM_M * XS_LD];   // xs[row][k], row stride 72
    __shared__ __half wsT[64   * WS_LD];   // wsT[n][k],  n stride 72

    const int tid  = threadIdx.x;
    const int lane = tid & 31;
    const int warp = tid >> 5;
    const int base = blockIdx.x * GM_M;
    const int g = lane >> 2;     // group id (row within m8)
    const int t = lane & 3;      // thread in group (k pair)
    const int wrow = warp * 16;

    float acc[8][4];
    #pragma unroll
    for (int i = 0; i < 8; ++i)
        #pragma unroll
        for (int j = 0; j < 4; ++j) acc[i][j] = 0.0f;

    for (int kk = 0; kk < F_IN; kk += 64) {
        // stage x tile (fp32 -> fp16)
        {
            const int r0 = tid >> 4;      // 0..15
            const int c  = tid & 15;      // float4 column
            #pragma unroll
            for (int rr = 0; rr < GM_M; rr += 16) {
                int r = rr + r0;
                int node = base + r;
                float4 v = make_float4(0.f, 0.f, 0.f, 0.f);
                if (node < N_NODES)
                    v = *(const float4*)&x[(size_t)node * F_IN + kk + c * 4];
                __half2 h0 = __floats2half2_rn(v.x, v.y);
                __half2 h1 = __floats2half2_rn(v.z, v.w);
                uint2 u;
                u.x = *(uint32_t*)&h0;
                u.y = *(uint32_t*)&h1;
                *(uint2*)&xs[r * XS_LD + c * 4] = u;
            }
        }
        // stage W tile transposed (fp32 -> fp16)
        for (int i = tid; i < 64 * 64; i += 256) {
            int k = i >> 6, n = i & 63;
            wsT[n * WS_LD + k] = __float2half(W[(size_t)(kk + k) * 64 + n]);
        }
        __syncthreads();

        #pragma unroll
        for (int ks = 0; ks < 4; ++ks) {
            const int K0 = ks * 16;
            uint32_t a0 = *(const uint32_t*)&xs[(wrow + g    ) * XS_LD + K0 +     2 * t];
            uint32_t a1 = *(const uint32_t*)&xs[(wrow + g + 8) * XS_LD + K0 +     2 * t];
            uint32_t a2 = *(const uint32_t*)&xs[(wrow + g    ) * XS_LD + K0 + 8 + 2 * t];
            uint32_t a3 = *(const uint32_t*)&xs[(wrow + g + 8) * XS_LD + K0 + 8 + 2 * t];
            #pragma unroll
            for (int nt = 0; nt < 8; ++nt) {
                uint32_t b0 = *(const uint32_t*)&wsT[(nt * 8 + g) * WS_LD + K0 +     2 * t];
                uint32_t b1 = *(const uint32_t*)&wsT[(nt * 8 + g) * WS_LD + K0 + 8 + 2 * t];
                asm volatile(
                    "mma.sync.aligned.m16n8k16.row.col.f32.f16.f16.f32 "
                    "{%0,%1,%2,%3}, {%4,%5,%6,%7}, {%8,%9}, {%0,%1,%2,%3};"
                    : "+f"(acc[nt][0]), "+f"(acc[nt][1]),
                      "+f"(acc[nt][2]), "+f"(acc[nt][3])
                    : "r"(a0), "r"(a1), "r"(a2), "r"(a3), "r"(b0), "r"(b1));
            }
        }
        __syncthreads();
    }

    // epilogue: c0,c1 -> row g col 2t,2t+1 ; c2,c3 -> row g+8
    int n0 = base + wrow + g;
    int n1 = n0 + 8;
    #pragma unroll
    for (int nt = 0; nt < 8; ++nt) {
        if (n0 < N_NODES) {
            __half2 h = __floats2half2_rn(acc[nt][0], acc[nt][1]);
            *(uint32_t*)&g_Hs[(size_t)n0 * F_H + nt * 8 + 2 * t] = *(uint32_t*)&h;
        }
        if (n1 < N_NODES) {
            __half2 h = __floats2half2_rn(acc[nt][2], acc[nt][3]);
            *(uint32_t*)&g_Hs[(size_t)n1 * F_H + nt * 8 + 2 * t] = *(uint32_t*)&h;
        }
    }
}

// ---------------- aggregate v3: warp/node, 4 oct-streams, uint4 rows ----------------
__device__ __forceinline__ void acc_row8(float* a, uint4 r, float ds) {
    float2 f;
    f = __half22float2(*(__half2*)&r.x); a[0] = fmaf(f.x, ds, a[0]); a[1] = fmaf(f.y, ds, a[1]);
    f = __half22float2(*(__half2*)&r.y); a[2] = fmaf(f.x, ds, a[2]); a[3] = fmaf(f.y, ds, a[3]);
    f = __half22float2(*(__half2*)&r.z); a[4] = fmaf(f.x, ds, a[4]); a[5] = fmaf(f.y, ds, a[5]);
    f = __half22float2(*(__half2*)&r.w); a[6] = fmaf(f.x, ds, a[6]); a[7] = fmaf(f.y, ds, a[7]);
}

__global__ __launch_bounds__(256) void aggregate_kernel() {
    int w = blockIdx.x * 8 + (threadIdx.x >> 5);
    if (w >= N_NODES) return;
    const int lane = threadIdx.x & 31;
    const int st = lane >> 3;   // stream 0..3
    const int q  = lane & 7;    // uint4 (16B) index within 128B row

    const uint4* __restrict__ H = (const uint4*)g_Hs;  // 8 uint4 per row
    const float dv = g_dinv[w];

    float acc[8] = {0.f, 0.f, 0.f, 0.f, 0.f, 0.f, 0.f, 0.f};
    if (st == 0) {
        uint4 r = H[(size_t)w * 8 + q];
        acc_row8(acc, r, dv);                 // self-loop term
    }

    const int beg = g_rowptr[w], end = g_rowptr[w + 1];
    int i = beg + st;
    for (; i + 4 < end; i += 8) {             // 2 neighbors in flight per stream
        int s0 = g_esrc[i];
        int s1 = g_esrc[i + 4];
        float d0 = g_dinv[s0];
        float d1 = g_dinv[s1];
        uint4 r0 = H[(size_t)s0 * 8 + q];
        uint4 r1 = H[(size_t)s1 * 8 + q];
        acc_row8(acc, r0, d0);
        acc_row8(acc, r1, d1);
    }
    if (i < end) {
        int s = g_esrc[i];
        float ds = g_dinv[s];
        uint4 r = H[(size_t)s * 8 + q];
        acc_row8(acc, r, ds);
    }

    // combine 4 streams
    #pragma unroll
    for (int j = 0; j < 8; ++j) {
        acc[j] += __shfl_xor_sync(0xffffffffu, acc[j], 8);
        acc[j] += __shfl_xor_sync(0xffffffffu, acc[j], 16);
    }

    if (st == 0) {
        float4 o0 = make_float4(acc[0] * dv, acc[1] * dv, acc[2] * dv, acc[3] * dv);
        float4 o1 = make_float4(acc[4] * dv, acc[5] * dv, acc[6] * dv, acc[7] * dv);
        ((float4*)g_ACC)[(size_t)w * 16 + q * 2]     = o0;
        ((float4*)g_ACC)[(size_t)w * 16 + q * 2 + 1] = o1;
    }
}

// ---------------- fused ReLU + MLP 64->32->16->10 ----------------
__global__ __launch_bounds__(128) void mlp_kernel(
    const float* __restrict__ b_gcn,
    const float* __restrict__ W1, const float* __restrict__ b1,
    const float* __restrict__ W2, const float* __restrict__ b2,
    const float* __restrict__ W3, const float* __restrict__ b3,
    float* __restrict__ out)
{
    __shared__ float sW1[64 * 32];
    __shared__ float sW2[32 * 16];
    __shared__ float sW3[16 * 10];
    __shared__ float sbg[64], sb1[32], sb2[16], sb3[10];

    const int tid = threadIdx.x;
    for (int i = tid; i < 64 * 32; i += 128) sW1[i] = W1[i];
    for (int i = tid; i < 32 * 16; i += 128) sW2[i] = W2[i];
    for (int i = tid; i < 16 * 10; i += 128) sW3[i] = W3[i];
    if (tid < 64) sbg[tid] = b_gcn[tid];
    if (tid < 32) sb1[tid] = b1[tid];
    if (tid < 16) sb2[tid] = b2[tid];
    if (tid < 10) sb3[tid] = b3[tid];
    __syncthreads();

    int node = blockIdx.x * 128 + tid;
    if (node >= N_NODES) return;

    float in[64];
    const float4* A4 = (const float4*)g_ACC;
    #pragma unroll
    for (int q = 0; q < 16; ++q) {
        float4 v = A4[(size_t)node * 16 + q];
        in[4 * q + 0] = fmaxf(v.x + sbg[4 * q + 0], 0.0f);
        in[4 * q + 1] = fmaxf(v.y + sbg[4 * q + 1], 0.0f);
        in[4 * q + 2] = fmaxf(v.z + sbg[4 * q + 2], 0.0f);
        in[4 * q + 3] = fmaxf(v.w + sbg[4 * q + 3], 0.0f);
    }

    float h1[32];
    #pragma unroll
    for (int j = 0; j < 32; ++j) h1[j] = sb1[j];
    #pragma unroll
    for (int k = 0; k < 64; ++k) {
        float a = in[k];
        #pragma unroll
        for (int j = 0; j < 32; ++j) h1[j] += a * sW1[k * 32 + j];
    }
    #pragma unroll
    for (int j = 0; j < 32; ++j) h1[j] = fmaxf(h1[j], 0.0f);

    float h2[16];
    #pragma unroll
    for (int j = 0; j < 16; ++j) h2[j] = sb2[j];
    #pragma unroll
    for (int k = 0; k < 32; ++k) {
        float a = h1[k];
        #pragma unroll
        for (int j = 0; j < 16; ++j) h2[j] += a * sW2[k * 16 + j];
    }
    #pragma unroll
    for (int j = 0; j < 16; ++j) h2[j] = fmaxf(h2[j], 0.0f);

    float o[10];
    #pragma unroll
    for (int j = 0; j < 10; ++j) o[j] = sb3[j];
    #pragma unroll
    for (int k = 0; k < 16; ++k) {
        float a = h2[k];
        #pragma unroll
        for (int j = 0; j < 10; ++j) o[j] += a * sW3[k * 10 + j];
    }
    #pragma unroll
    for (int j = 0; j < 10; ++j) out[(size_t)node * 10 + j] = o[j];
}

// ---------------- launcher ----------------
extern "C" void kernel_launch(void* const* d_in, const int* in_sizes, int n_in,
                              void* d_out, int out_size)
{
    const float* x     = (const float*)d_in[0];
    const void*  ei    = d_in[1];
    const float* W_gcn = (const float*)d_in[2];
    const float* b_gcn = (const float*)d_in[3];
    const float* W1    = (const float*)d_in[4];
    const float* b1    = (const float*)d_in[5];
    const float* W2    = (const float*)d_in[6];
    const float* b2    = (const float*)d_in[7];
    const float* W3    = (const float*)d_in[8];
    const float* b3    = (const float*)d_in[9];
    float* out = (float*)d_out;

    detect_kernel<<<1, 32>>>((const int*)ei);
    zero_cnt_kernel<<<NB, 256>>>();
    count_kernel<<<(N_EDGES + 255) / 256, 256>>>(ei);
    bsum_kernel<<<NB, 256>>>();
    bscan_kernel<<<1, 512>>>();
    rowptr_kernel<<<NB, 256>>>();
    csr_kernel<<<(N_EDGES + 255) / 256, 256>>>(ei);
    gemm_kernel<<<(N_NODES + GM_M - 1) / GM_M, 256>>>(x, W_gcn);
    aggregate_kernel<<<(N_NODES + 7) / 8, 256>>>();
    mlp_kernel<<<(N_NODES + 127) / 128, 128>>>(b_gcn, W1, b1, W2, b2, W3, b3, out);
}

// round 5
// speedup vs baseline: 2.2134x; 1.0294x over previous
#include <cuda_runtime.h>
#include <cuda_fp16.h>
#include <cstdint>

#define N_NODES 100000
#define N_EDGES 3200000
#define F_IN    256
#define F_H     64
#define NB      391   // ceil(N_NODES/256)

// ---------------- scratch (device globals: allocation-free) ----------------
__device__ __align__(16) __half g_Hs [(size_t)N_NODES * F_H];
__device__ __align__(16) float  g_ACC[(size_t)N_NODES * F_H];
__device__ float g_dinv[N_NODES];
__device__ int   g_cnt [N_NODES];
__device__ int   g_bsum[NB];
__device__ int   g_boff[NB];
__device__ int   g_rowptr[N_NODES + 1];
__device__ int   g_fill[N_NODES];
__device__ int   g_esrc[N_EDGES];
__device__ int   g_is64;

__device__ __forceinline__ int load_idx(const void* ei, size_t pos, int is64) {
    if (is64) return (int)((const long long*)ei)[pos];
    return ((const int*)ei)[pos];
}

// ---------------- zero counters + dtype sniff (fused) ----------------
__global__ void zero_detect_kernel(const int* __restrict__ ei32) {
    int n = blockIdx.x * blockDim.x + threadIdx.x;
    if (n < N_NODES) g_cnt[n] = 0;
    if (blockIdx.x == 0 && threadIdx.x == 0) {
        int ok64 = 1;
        #pragma unroll
        for (int i = 0; i < 8; ++i)
            if (ei32[2 * i + 1] != 0) ok64 = 0;
        g_is64 = ok64;
    }
}

// ---------------- degree count (dst side) ----------------
__global__ void count_kernel(const void* __restrict__ ei) {
    int e = blockIdx.x * blockDim.x + threadIdx.x;
    if (e >= N_EDGES) return;
    const int is64 = g_is64;
    int d = load_idx(ei, (size_t)N_EDGES + e, is64);
    atomicAdd(&g_cnt[d], 1);
}

// ---------------- scan phase 1: block sums + dinv ----------------
__global__ __launch_bounds__(256) void bsum_kernel() {
    __shared__ int red[256];
    int t = threadIdx.x;
    int idx = blockIdx.x * 256 + t;
    int c = (idx < N_NODES) ? g_cnt[idx] : 0;
    if (idx < N_NODES) g_dinv[idx] = rsqrtf((float)c + 1.0f);
    red[t] = c;
    __syncthreads();
    #pragma unroll
    for (int off = 128; off; off >>= 1) {
        if (t < off) red[t] += red[t + off];
        __syncthreads();
    }
    if (t == 0) g_bsum[blockIdx.x] = red[0];
}

// ---------------- scan phase 2: scan 391 block sums (1 block) ----------------
__global__ __launch_bounds__(512) void bscan_kernel() {
    __shared__ int s[512];
    int t = threadIdx.x;
    int v = (t < NB) ? g_bsum[t] : 0;
    s[t] = v;
    __syncthreads();
    #pragma unroll
    for (int off = 1; off < 512; off <<= 1) {
        int u = (t >= off) ? s[t - off] : 0;
        __syncthreads();
        s[t] += u;
        __syncthreads();
    }
    if (t < NB) g_boff[t] = s[t] - v;   // exclusive
}

// ---------------- scan phase 3: per-block exclusive scan -> rowptr ----------------
__global__ __launch_bounds__(256) void rowptr_kernel() {
    __shared__ int s[256];
    int t = threadIdx.x;
    int idx = blockIdx.x * 256 + t;
    int c = (idx < N_NODES) ? g_cnt[idx] : 0;
    s[t] = c;
    __syncthreads();
    #pragma unroll
    for (int off = 1; off < 256; off <<= 1) {
        int u = (t >= off) ? s[t - off] : 0;
        __syncthreads();
        s[t] += u;
        __syncthreads();
    }
    int ex = g_boff[blockIdx.x] + s[t] - c;
    if (idx < N_NODES) {
        g_rowptr[idx] = ex;
        g_fill[idx]   = ex;
        if (idx == N_NODES - 1) g_rowptr[N_NODES] = ex + c;
    }
}

// ---------------- CSR scatter: sort edge srcs into dst buckets ----------------
__global__ void csr_kernel(const void* __restrict__ ei) {
    int e = blockIdx.x * blockDim.x + threadIdx.x;
    if (e >= N_EDGES) return;
    const int is64 = g_is64;
    int s = load_idx(ei, (size_t)e, is64);
    int d = load_idx(ei, (size_t)N_EDGES + e, is64);
    int pos = atomicAdd(&g_fill[d], 1);
    g_esrc[pos] = s;
}

// ---------------- HMMA GEMM v2: double-buffered, reg prefetch ----------------
// Block tile 128x64, K-tile 64, 8 warps (each warp: 16 rows x 64 cols).
#define GM_M   128
#define XS_LD  72
#define WS_LD  72

__global__ __launch_bounds__(256) void gemm_kernel(
    const float* __restrict__ x, const float* __restrict__ W)
{
    __shared__ __half xs [2][GM_M * XS_LD];   // xs[b][row][k], row stride 72
    __shared__ __half wsT[2][64   * WS_LD];   // wsT[b][n][k],  n stride 72

    const int tid  = threadIdx.x;
    const int lane = tid & 31;
    const int warp = tid >> 5;
    const int base = blockIdx.x * GM_M;
    const int g = lane >> 2;
    const int t = lane & 3;
    const int wrow = warp * 16;
    const int r0 = tid >> 4;   // 0..15 (x stage row)
    const int c  = tid & 15;   // float4 column

    float4 xr[8];
    float  wr[16];

    auto load_tile = [&](int kk) {
        #pragma unroll
        for (int rr = 0; rr < 8; ++rr) {
            int node = base + rr * 16 + r0;
            float4 v = make_float4(0.f, 0.f, 0.f, 0.f);
            if (node < N_NODES)
                v = *(const float4*)&x[(size_t)node * F_IN + kk + c * 4];
            xr[rr] = v;
        }
        #pragma unroll
        for (int p = 0; p < 16; ++p) {
            int i = tid + p * 256;             // 0..4095
            int k = i >> 6, n = i & 63;
            wr[p] = W[(size_t)(kk + k) * 64 + n];
        }
    };
    auto store_tile = [&](int b) {
        #pragma unroll
        for (int rr = 0; rr < 8; ++rr) {
            __half2 h0 = __floats2half2_rn(xr[rr].x, xr[rr].y);
            __half2 h1 = __floats2half2_rn(xr[rr].z, xr[rr].w);
            uint2 u;
            u.x = *(uint32_t*)&h0;
            u.y = *(uint32_t*)&h1;
            *(uint2*)&xs[b][(rr * 16 + r0) * XS_LD + c * 4] = u;
        }
        #pragma unroll
        for (int p = 0; p < 16; ++p) {
            int i = tid + p * 256;
            int k = i >> 6, n = i & 63;
            wsT[b][n * WS_LD + k] = __float2half(wr[p]);
        }
    };

    float acc[8][4];
    #pragma unroll
    for (int i = 0; i < 8; ++i)
        #pragma unroll
        for (int j = 0; j < 4; ++j) acc[i][j] = 0.0f;

    load_tile(0);
    store_tile(0);

    #pragma unroll
    for (int kt = 0; kt < 4; ++kt) {
        __syncthreads();
        if (kt < 3) load_tile((kt + 1) * 64);   // global loads overlap MMA below
        const int b = kt & 1;

        #pragma unroll
        for (int ks = 0; ks < 4; ++ks) {
            const int K0 = ks * 16;
            uint32_t a0 = *(const uint32_t*)&xs[b][(wrow + g    ) * XS_LD + K0 +     2 * t];
            uint32_t a1 = *(const uint32_t*)&xs[b][(wrow + g + 8) * XS_LD + K0 +     2 * t];
            uint32_t a2 = *(const uint32_t*)&xs[b][(wrow + g    ) * XS_LD + K0 + 8 + 2 * t];
            uint32_t a3 = *(const uint32_t*)&xs[b][(wrow + g + 8) * XS_LD + K0 + 8 + 2 * t];
            #pragma unroll
            for (int nt = 0; nt < 8; ++nt) {
                uint32_t b0 = *(const uint32_t*)&wsT[b][(nt * 8 + g) * WS_LD + K0 +     2 * t];
                uint32_t b1 = *(const uint32_t*)&wsT[b][(nt * 8 + g) * WS_LD + K0 + 8 + 2 * t];
                asm volatile(
                    "mma.sync.aligned.m16n8k16.row.col.f32.f16.f16.f32 "
                    "{%0,%1,%2,%3}, {%4,%5,%6,%7}, {%8,%9}, {%0,%1,%2,%3};"
                    : "+f"(acc[nt][0]), "+f"(acc[nt][1]),
                      "+f"(acc[nt][2]), "+f"(acc[nt][3])
                    : "r"(a0), "r"(a1), "r"(a2), "r"(a3), "r"(b0), "r"(b1));
            }
        }
        if (kt < 3) store_tile(1 - b);          // write next buffer (disjoint)
    }

    int n0 = base + wrow + g;
    int n1 = n0 + 8;
    #pragma unroll
    for (int nt = 0; nt < 8; ++nt) {
        if (n0 < N_NODES) {
            __half2 h = __floats2half2_rn(acc[nt][0], acc[nt][1]);
            *(uint32_t*)&g_Hs[(size_t)n0 * F_H + nt * 8 + 2 * t] = *(uint32_t*)&h;
        }
        if (n1 < N_NODES) {
            __half2 h = __floats2half2_rn(acc[nt][2], acc[nt][3]);
            *(uint32_t*)&g_Hs[(size_t)n1 * F_H + nt * 8 + 2 * t] = *(uint32_t*)&h;
        }
    }
}

// ---------------- aggregate v3: warp/node, 4 oct-streams, uint4 rows ----------------
__device__ __forceinline__ void acc_row8(float* a, uint4 r, float ds) {
    float2 f;
    f = __half22float2(*(__half2*)&r.x); a[0] = fmaf(f.x, ds, a[0]); a[1] = fmaf(f.y, ds, a[1]);
    f = __half22float2(*(__half2*)&r.y); a[2] = fmaf(f.x, ds, a[2]); a[3] = fmaf(f.y, ds, a[3]);
    f = __half22float2(*(__half2*)&r.z); a[4] = fmaf(f.x, ds, a[4]); a[5] = fmaf(f.y, ds, a[5]);
    f = __half22float2(*(__half2*)&r.w); a[6] = fmaf(f.x, ds, a[6]); a[7] = fmaf(f.y, ds, a[7]);
}

__global__ __launch_bounds__(256) void aggregate_kernel() {
    int w = blockIdx.x * 8 + (threadIdx.x >> 5);
    if (w >= N_NODES) return;
    const int lane = threadIdx.x & 31;
    const int st = lane >> 3;
    const int q  = lane & 7;

    const uint4* __restrict__ H = (const uint4*)g_Hs;
    const float dv = g_dinv[w];

    float acc[8] = {0.f, 0.f, 0.f, 0.f, 0.f, 0.f, 0.f, 0.f};
    if (st == 0) {
        uint4 r = H[(size_t)w * 8 + q];
        acc_row8(acc, r, dv);
    }

    const int beg = g_rowptr[w], end = g_rowptr[w + 1];
    int i = beg + st;
    for (; i + 4 < end; i += 8) {
        int s0 = g_esrc[i];
        int s1 = g_esrc[i + 4];
        float d0 = g_dinv[s0];
        float d1 = g_dinv[s1];
        uint4 r0 = H[(size_t)s0 * 8 + q];
        uint4 r1 = H[(size_t)s1 * 8 + q];
        acc_row8(acc, r0, d0);
        acc_row8(acc, r1, d1);
    }
    if (i < end) {
        int s = g_esrc[i];
        float ds = g_dinv[s];
        uint4 r = H[(size_t)s * 8 + q];
        acc_row8(acc, r, ds);
    }

    #pragma unroll
    for (int j = 0; j < 8; ++j) {
        acc[j] += __shfl_xor_sync(0xffffffffu, acc[j], 8);
        acc[j] += __shfl_xor_sync(0xffffffffu, acc[j], 16);
    }

    if (st == 0) {
        float4 o0 = make_float4(acc[0] * dv, acc[1] * dv, acc[2] * dv, acc[3] * dv);
        float4 o1 = make_float4(acc[4] * dv, acc[5] * dv, acc[6] * dv, acc[7] * dv);
        ((float4*)g_ACC)[(size_t)w * 16 + q * 2]     = o0;
        ((float4*)g_ACC)[(size_t)w * 16 + q * 2 + 1] = o1;
    }
}

// ---------------- fused ReLU + MLP 64->32->16->10 (vectorized weights) ----------------
__global__ __launch_bounds__(128) void mlp_kernel(
    const float* __restrict__ b_gcn,
    const float* __restrict__ W1, const float* __restrict__ b1,
    const float* __restrict__ W2, const float* __restrict__ b2,
    const float* __restrict__ W3, const float* __restrict__ b3,
    float* __restrict__ out)
{
    __shared__ __align__(16) float sW1[64 * 32];
    __shared__ __align__(16) float sW2[32 * 16];
    __shared__ __align__(16) float sW3[16 * 10];
    __shared__ float sbg[64], sb1[32], sb2[16], sb3[10];

    const int tid = threadIdx.x;
    for (int i = tid; i < 64 * 32; i += 128) sW1[i] = W1[i];
    for (int i = tid; i < 32 * 16; i += 128) sW2[i] = W2[i];
    for (int i = tid; i < 16 * 10; i += 128) sW3[i] = W3[i];
    if (tid < 64) sbg[tid] = b_gcn[tid];
    if (tid < 32) sb1[tid] = b1[tid];
    if (tid < 16) sb2[tid] = b2[tid];
    if (tid < 10) sb3[tid] = b3[tid];
    __syncthreads();

    int node = blockIdx.x * 128 + tid;
    if (node >= N_NODES) return;

    float in[64];
    const float4* A4 = (const float4*)g_ACC;
    #pragma unroll
    for (int q = 0; q < 16; ++q) {
        float4 v = A4[(size_t)node * 16 + q];
        in[4 * q + 0] = fmaxf(v.x + sbg[4 * q + 0], 0.0f);
        in[4 * q + 1] = fmaxf(v.y + sbg[4 * q + 1], 0.0f);
        in[4 * q + 2] = fmaxf(v.z + sbg[4 * q + 2], 0.0f);
        in[4 * q + 3] = fmaxf(v.w + sbg[4 * q + 3], 0.0f);
    }

    float h1[32];
    #pragma unroll
    for (int j = 0; j < 32; ++j) h1[j] = sb1[j];
    #pragma unroll
    for (int k = 0; k < 64; ++k) {
        float a = in[k];
        #pragma unroll
        for (int j4 = 0; j4 < 8; ++j4) {
            float4 wv = *(const float4*)&sW1[k * 32 + j4 * 4];
            h1[j4 * 4 + 0] = fmaf(a, wv.x, h1[j4 * 4 + 0]);
            h1[j4 * 4 + 1] = fmaf(a, wv.y, h1[j4 * 4 + 1]);
            h1[j4 * 4 + 2] = fmaf(a, wv.z, h1[j4 * 4 + 2]);
            h1[j4 * 4 + 3] = fmaf(a, wv.w, h1[j4 * 4 + 3]);
        }
    }
    #pragma unroll
    for (int j = 0; j < 32; ++j) h1[j] = fmaxf(h1[j], 0.0f);

    float h2[16];
    #pragma unroll
    for (int j = 0; j < 16; ++j) h2[j] = sb2[j];
    #pragma unroll
    for (int k = 0; k < 32; ++k) {
        float a = h1[k];
        #pragma unroll
        for (int j4 = 0; j4 < 4; ++j4) {
            float4 wv = *(const float4*)&sW2[k * 16 + j4 * 4];
            h2[j4 * 4 + 0] = fmaf(a, wv.x, h2[j4 * 4 + 0]);
            h2[j4 * 4 + 1] = fmaf(a, wv.y, h2[j4 * 4 + 1]);
            h2[j4 * 4 + 2] = fmaf(a, wv.z, h2[j4 * 4 + 2]);
            h2[j4 * 4 + 3] = fmaf(a, wv.w, h2[j4 * 4 + 3]);
        }
    }
    #pragma unroll
    for (int j = 0; j < 16; ++j) h2[j] = fmaxf(h2[j], 0.0f);

    float o[10];
    #pragma unroll
    for (int j = 0; j < 10; ++j) o[j] = sb3[j];
    #pragma unroll
    for (int k = 0; k < 16; ++k) {
        float a = h2[k];
        #pragma unroll
        for (int j2 = 0; j2 < 5; ++j2) {
            float2 wv = *(const float2*)&sW3[k * 10 + j2 * 2];
            o[j2 * 2 + 0] = fmaf(a, wv.x, o[j2 * 2 + 0]);
            o[j2 * 2 + 1] = fmaf(a, wv.y, o[j2 * 2 + 1]);
        }
    }
    #pragma unroll
    for (int j = 0; j < 10; ++j) out[(size_t)node * 10 + j] = o[j];
}

// ---------------- launcher ----------------
extern "C" void kernel_launch(void* const* d_in, const int* in_sizes, int n_in,
                              void* d_out, int out_size)
{
    const float* x     = (const float*)d_in[0];
    const void*  ei    = d_in[1];
    const float* W_gcn = (const float*)d_in[2];
    const float* b_gcn = (const float*)d_in[3];
    const float* W1    = (const float*)d_in[4];
    const float* b1    = (const float*)d_in[5];
    const float* W2    = (const float*)d_in[6];
    const float* b2    = (const float*)d_in[7];
    const float* W3    = (const float*)d_in[8];
    const float* b3    = (const float*)d_in[9];
    float* out = (float*)d_out;

    zero_detect_kernel<<<NB, 256>>>((const int*)ei);
    count_kernel<<<(N_EDGES + 255) / 256, 256>>>(ei);
    bsum_kernel<<<NB, 256>>>();
    bscan_kernel<<<1, 512>>>();
    rowptr_kernel<<<NB, 256>>>();
    csr_kernel<<<(N_EDGES + 255) / 256, 256>>>(ei);
    gemm_kernel<<<(N_NODES + GM_M - 1) / GM_M, 256>>>(x, W_gcn);
    aggregate_kernel<<<(N_NODES + 7) / 8, 256>>>();
    mlp_kernel<<<(N_NODES + 127) / 128, 128>>>(b_gcn, W1, b1, W2, b2, W3, b3, out);
}

// round 6
// speedup vs baseline: 2.2732x; 1.0270x over previous
#include <cuda_runtime.h>
#include <cuda_fp16.h>
#include <cstdint>

#define N_NODES 100000
#define N_EDGES 3200000
#define F_IN    256
#define F_H     64
#define NB      391   // ceil(N_NODES/256)

// ---------------- scratch (device globals: allocation-free) ----------------
__device__ __align__(16) __half g_Hs [(size_t)N_NODES * F_H];
__device__ __align__(16) float  g_ACC[(size_t)N_NODES * F_H];
__device__ float g_dinv[N_NODES];
__device__ int   g_cnt [N_NODES];
__device__ int   g_bsum[NB];
__device__ int   g_rowptr[N_NODES + 1];
__device__ int   g_fill[N_NODES];
__device__ int   g_esrc[N_EDGES];
__device__ int   g_is64;

__device__ __forceinline__ int load_idx(const void* ei, size_t pos, int is64) {
    if (is64) return (int)((const long long*)ei)[pos];
    return ((const int*)ei)[pos];
}

// ---------------- zero counters + dtype sniff (fused) ----------------
__global__ void zero_detect_kernel(const int* __restrict__ ei32) {
    int n = blockIdx.x * blockDim.x + threadIdx.x;
    if (n < N_NODES) g_cnt[n] = 0;
    if (blockIdx.x == 0 && threadIdx.x == 0) {
        int ok64 = 1;
        #pragma unroll
        for (int i = 0; i < 8; ++i)
            if (ei32[2 * i + 1] != 0) ok64 = 0;
        g_is64 = ok64;
    }
}

// ---------------- degree count (dst side) ----------------
__global__ void count_kernel(const void* __restrict__ ei) {
    int e = blockIdx.x * blockDim.x + threadIdx.x;
    if (e >= N_EDGES) return;
    const int is64 = g_is64;
    int d = load_idx(ei, (size_t)N_EDGES + e, is64);
    atomicAdd(&g_cnt[d], 1);
}

// ---------------- scan phase 1: block sums + dinv ----------------
__global__ __launch_bounds__(256) void bsum_kernel() {
    __shared__ int red[256];
    int t = threadIdx.x;
    int idx = blockIdx.x * 256 + t;
    int c = (idx < N_NODES) ? g_cnt[idx] : 0;
    if (idx < N_NODES) g_dinv[idx] = rsqrtf((float)c + 1.0f);
    red[t] = c;
    __syncthreads();
    #pragma unroll
    for (int off = 128; off; off >>= 1) {
        if (t < off) red[t] += red[t + off];
        __syncthreads();
    }
    if (t == 0) g_bsum[blockIdx.x] = red[0];
}

// ---------------- scan phase 2: rowptr (per-block scan + inline prefix reduce) --
__global__ __launch_bounds__(256) void rowptr_kernel() {
    __shared__ int s[256];
    __shared__ int red[256];
    __shared__ int s_prev;
    const int t = threadIdx.x;
    const int idx = blockIdx.x * 256 + t;

    // sum of bsum[0 .. blockIdx.x-1]  (<=390 ints, strided + block reduce)
    int p = 0;
    for (int i = t; i < blockIdx.x; i += 256) p += g_bsum[i];
    red[t] = p;
    __syncthreads();
    #pragma unroll
    for (int off = 128; off; off >>= 1) {
        if (t < off) red[t] += red[t + off];
        __syncthreads();
    }
    if (t == 0) s_prev = red[0];

    int c = (idx < N_NODES) ? g_cnt[idx] : 0;
    s[t] = c;
    __syncthreads();
    #pragma unroll
    for (int off = 1; off < 256; off <<= 1) {
        int u = (t >= off) ? s[t - off] : 0;
        __syncthreads();
        s[t] += u;
        __syncthreads();
    }
    int ex = s_prev + s[t] - c;
    if (idx < N_NODES) {
        g_rowptr[idx] = ex;
        g_fill[idx]   = ex;
        if (idx == N_NODES - 1) g_rowptr[N_NODES] = ex + c;
    }
}

// ---------------- CSR scatter: sort edge srcs into dst buckets ----------------
__global__ void csr_kernel(const void* __restrict__ ei) {
    int e = blockIdx.x * blockDim.x + threadIdx.x;
    if (e >= N_EDGES) return;
    const int is64 = g_is64;
    int s = load_idx(ei, (size_t)e, is64);
    int d = load_idx(ei, (size_t)N_EDGES + e, is64);
    int pos = atomicAdd(&g_fill[d], 1);
    g_esrc[pos] = s;
}

// ---------------- HMMA GEMM v2: double-buffered, reg prefetch ----------------
#define GM_M   128
#define XS_LD  72
#define WS_LD  72

__global__ __launch_bounds__(256) void gemm_kernel(
    const float* __restrict__ x, const float* __restrict__ W)
{
    __shared__ __half xs [2][GM_M * XS_LD];
    __shared__ __half wsT[2][64   * WS_LD];

    const int tid  = threadIdx.x;
    const int lane = tid & 31;
    const int warp = tid >> 5;
    const int base = blockIdx.x * GM_M;
    const int g = lane >> 2;
    const int t = lane & 3;
    const int wrow = warp * 16;
    const int r0 = tid >> 4;
    const int c  = tid & 15;

    float4 xr[8];
    float  wr[16];

    auto load_tile = [&](int kk) {
        #pragma unroll
        for (int rr = 0; rr < 8; ++rr) {
            int node = base + rr * 16 + r0;
            float4 v = make_float4(0.f, 0.f, 0.f, 0.f);
            if (node < N_NODES)
                v = *(const float4*)&x[(size_t)node * F_IN + kk + c * 4];
            xr[rr] = v;
        }
        #pragma unroll
        for (int p = 0; p < 16; ++p) {
            int i = tid + p * 256;
            int k = i >> 6, n = i & 63;
            wr[p] = W[(size_t)(kk + k) * 64 + n];
        }
    };
    auto store_tile = [&](int b) {
        #pragma unroll
        for (int rr = 0; rr < 8; ++rr) {
            __half2 h0 = __floats2half2_rn(xr[rr].x, xr[rr].y);
            __half2 h1 = __floats2half2_rn(xr[rr].z, xr[rr].w);
            uint2 u;
            u.x = *(uint32_t*)&h0;
            u.y = *(uint32_t*)&h1;
            *(uint2*)&xs[b][(rr * 16 + r0) * XS_LD + c * 4] = u;
        }
        #pragma unroll
        for (int p = 0; p < 16; ++p) {
            int i = tid + p * 256;
            int k = i >> 6, n = i & 63;
            wsT[b][n * WS_LD + k] = __float2half(wr[p]);
        }
    };

    float acc[8][4];
    #pragma unroll
    for (int i = 0; i < 8; ++i)
        #pragma unroll
        for (int j = 0; j < 4; ++j) acc[i][j] = 0.0f;

    load_tile(0);
    store_tile(0);

    #pragma unroll
    for (int kt = 0; kt < 4; ++kt) {
        __syncthreads();
        if (kt < 3) load_tile((kt + 1) * 64);
        const int b = kt & 1;

        #pragma unroll
        for (int ks = 0; ks < 4; ++ks) {
            const int K0 = ks * 16;
            uint32_t a0 = *(const uint32_t*)&xs[b][(wrow + g    ) * XS_LD + K0 +     2 * t];
            uint32_t a1 = *(const uint32_t*)&xs[b][(wrow + g + 8) * XS_LD + K0 +     2 * t];
            uint32_t a2 = *(const uint32_t*)&xs[b][(wrow + g    ) * XS_LD + K0 + 8 + 2 * t];
            uint32_t a3 = *(const uint32_t*)&xs[b][(wrow + g + 8) * XS_LD + K0 + 8 + 2 * t];
            #pragma unroll
            for (int nt = 0; nt < 8; ++nt) {
                uint32_t b0 = *(const uint32_t*)&wsT[b][(nt * 8 + g) * WS_LD + K0 +     2 * t];
                uint32_t b1 = *(const uint32_t*)&wsT[b][(nt * 8 + g) * WS_LD + K0 + 8 + 2 * t];
                asm volatile(
                    "mma.sync.aligned.m16n8k16.row.col.f32.f16.f16.f32 "
                    "{%0,%1,%2,%3}, {%4,%5,%6,%7}, {%8,%9}, {%0,%1,%2,%3};"
                    : "+f"(acc[nt][0]), "+f"(acc[nt][1]),
                      "+f"(acc[nt][2]), "+f"(acc[nt][3])
                    : "r"(a0), "r"(a1), "r"(a2), "r"(a3), "r"(b0), "r"(b1));
            }
        }
        if (kt < 3) store_tile(1 - b);
    }

    int n0 = base + wrow + g;
    int n1 = n0 + 8;
    #pragma unroll
    for (int nt = 0; nt < 8; ++nt) {
        if (n0 < N_NODES) {
            __half2 h = __floats2half2_rn(acc[nt][0], acc[nt][1]);
            *(uint32_t*)&g_Hs[(size_t)n0 * F_H + nt * 8 + 2 * t] = *(uint32_t*)&h;
        }
        if (n1 < N_NODES) {
            __half2 h = __floats2half2_rn(acc[nt][2], acc[nt][3]);
            *(uint32_t*)&g_Hs[(size_t)n1 * F_H + nt * 8 + 2 * t] = *(uint32_t*)&h;
        }
    }
}

// ---------------- aggregate v3: warp/node, 4 oct-streams, uint4 rows ----------------
__device__ __forceinline__ void acc_row8(float* a, uint4 r, float ds) {
    float2 f;
    f = __half22float2(*(__half2*)&r.x); a[0] = fmaf(f.x, ds, a[0]); a[1] = fmaf(f.y, ds, a[1]);
    f = __half22float2(*(__half2*)&r.y); a[2] = fmaf(f.x, ds, a[2]); a[3] = fmaf(f.y, ds, a[3]);
    f = __half22float2(*(__half2*)&r.z); a[4] = fmaf(f.x, ds, a[4]); a[5] = fmaf(f.y, ds, a[5]);
    f = __half22float2(*(__half2*)&r.w); a[6] = fmaf(f.x, ds, a[6]); a[7] = fmaf(f.y, ds, a[7]);
}

__global__ __launch_bounds__(256) void aggregate_kernel() {
    int w = blockIdx.x * 8 + (threadIdx.x >> 5);
    if (w >= N_NODES) return;
    const int lane = threadIdx.x & 31;
    const int st = lane >> 3;
    const int q  = lane & 7;

    const uint4* __restrict__ H = (const uint4*)g_Hs;
    const float dv = g_dinv[w];

    float acc[8] = {0.f, 0.f, 0.f, 0.f, 0.f, 0.f, 0.f, 0.f};
    if (st == 0) {
        uint4 r = H[(size_t)w * 8 + q];
        acc_row8(acc, r, dv);
    }

    const int beg = g_rowptr[w], end = g_rowptr[w + 1];
    int i = beg + st;
    for (; i + 4 < end; i += 8) {
        int s0 = g_esrc[i];
        int s1 = g_esrc[i + 4];
        float d0 = g_dinv[s0];
        float d1 = g_dinv[s1];
        uint4 r0 = H[(size_t)s0 * 8 + q];
        uint4 r1 = H[(size_t)s1 * 8 + q];
        acc_row8(acc, r0, d0);
        acc_row8(acc, r1, d1);
    }
    if (i < end) {
        int s = g_esrc[i];
        float ds = g_dinv[s];
        uint4 r = H[(size_t)s * 8 + q];
        acc_row8(acc, r, ds);
    }

    #pragma unroll
    for (int j = 0; j < 8; ++j) {
        acc[j] += __shfl_xor_sync(0xffffffffu, acc[j], 8);
        acc[j] += __shfl_xor_sync(0xffffffffu, acc[j], 16);
    }

    if (st == 0) {
        float4 o0 = make_float4(acc[0] * dv, acc[1] * dv, acc[2] * dv, acc[3] * dv);
        float4 o1 = make_float4(acc[4] * dv, acc[5] * dv, acc[6] * dv, acc[7] * dv);
        ((float4*)g_ACC)[(size_t)w * 16 + q * 2]     = o0;
        ((float4*)g_ACC)[(size_t)w * 16 + q * 2 + 1] = o1;
    }
}

// ---------------- fused ReLU + MLP 64->32->16->10 (vectorized weights) ----------------
__global__ __launch_bounds__(128) void mlp_kernel(
    const float* __restrict__ b_gcn,
    const float* __restrict__ W1, const float* __restrict__ b1,
    const float* __restrict__ W2, const float* __restrict__ b2,
    const float* __restrict__ W3, const float* __restrict__ b3,
    float* __restrict__ out)
{
    __shared__ __align__(16) float sW1[64 * 32];
    __shared__ __align__(16) float sW2[32 * 16];
    __shared__ __align__(16) float sW3[16 * 10];
    __shared__ float sbg[64], sb1[32], sb2[16], sb3[10];

    const int tid = threadIdx.x;
    for (int i = tid; i < 64 * 32; i += 128) sW1[i] = W1[i];
    for (int i = tid; i < 32 * 16; i += 128) sW2[i] = W2[i];
    for (int i = tid; i < 16 * 10; i += 128) sW3[i] = W3[i];
    if (tid < 64) sbg[tid] = b_gcn[tid];
    if (tid < 32) sb1[tid] = b1[tid];
    if (tid < 16) sb2[tid] = b2[tid];
    if (tid < 10) sb3[tid] = b3[tid];
    __syncthreads();

    int node = blockIdx.x * 128 + tid;
    if (node >= N_NODES) return;

    float in[64];
    const float4* A4 = (const float4*)g_ACC;
    #pragma unroll
    for (int q = 0; q < 16; ++q) {
        float4 v = A4[(size_t)node * 16 + q];
        in[4 * q + 0] = fmaxf(v.x + sbg[4 * q + 0], 0.0f);
        in[4 * q + 1] = fmaxf(v.y + sbg[4 * q + 1], 0.0f);
        in[4 * q + 2] = fmaxf(v.z + sbg[4 * q + 2], 0.0f);
        in[4 * q + 3] = fmaxf(v.w + sbg[4 * q + 3], 0.0f);
    }

    float h1[32];
    #pragma unroll
    for (int j = 0; j < 32; ++j) h1[j] = sb1[j];
    #pragma unroll
    for (int k = 0; k < 64; ++k) {
        float a = in[k];
        #pragma unroll
        for (int j4 = 0; j4 < 8; ++j4) {
            float4 wv = *(const float4*)&sW1[k * 32 + j4 * 4];
            h1[j4 * 4 + 0] = fmaf(a, wv.x, h1[j4 * 4 + 0]);
            h1[j4 * 4 + 1] = fmaf(a, wv.y, h1[j4 * 4 + 1]);
            h1[j4 * 4 + 2] = fmaf(a, wv.z, h1[j4 * 4 + 2]);
            h1[j4 * 4 + 3] = fmaf(a, wv.w, h1[j4 * 4 + 3]);
        }
    }
    #pragma unroll
    for (int j = 0; j < 32; ++j) h1[j] = fmaxf(h1[j], 0.0f);

    float h2[16];
    #pragma unroll
    for (int j = 0; j < 16; ++j) h2[j] = sb2[j];
    #pragma unroll
    for (int k = 0; k < 32; ++k) {
        float a = h1[k];
        #pragma unroll
        for (int j4 = 0; j4 < 4; ++j4) {
            float4 wv = *(const float4*)&sW2[k * 16 + j4 * 4];
            h2[j4 * 4 + 0] = fmaf(a, wv.x, h2[j4 * 4 + 0]);
            h2[j4 * 4 + 1] = fmaf(a, wv.y, h2[j4 * 4 + 1]);
            h2[j4 * 4 + 2] = fmaf(a, wv.z, h2[j4 * 4 + 2]);
            h2[j4 * 4 + 3] = fmaf(a, wv.w, h2[j4 * 4 + 3]);
        }
    }
    #pragma unroll
    for (int j = 0; j < 16; ++j) h2[j] = fmaxf(h2[j], 0.0f);

    float o[10];
    #pragma unroll
    for (int j = 0; j < 10; ++j) o[j] = sb3[j];
    #pragma unroll
    for (int k = 0; k < 16; ++k) {
        float a = h2[k];
        #pragma unroll
        for (int j2 = 0; j2 < 5; ++j2) {
            float2 wv = *(const float2*)&sW3[k * 10 + j2 * 2];
            o[j2 * 2 + 0] = fmaf(a, wv.x, o[j2 * 2 + 0]);
            o[j2 * 2 + 1] = fmaf(a, wv.y, o[j2 * 2 + 1]);
        }
    }
    #pragma unroll
    for (int j = 0; j < 10; ++j) out[(size_t)node * 10 + j] = o[j];
}

// ---------------- launcher (fork-join: GEMM || degree/CSR chain) ----------------
extern "C" void kernel_launch(void* const* d_in, const int* in_sizes, int n_in,
                              void* d_out, int out_size)
{
    const float* x     = (const float*)d_in[0];
    const void*  ei    = d_in[1];
    const float* W_gcn = (const float*)d_in[2];
    const float* b_gcn = (const float*)d_in[3];
    const float* W1    = (const float*)d_in[4];
    const float* b1    = (const float*)d_in[5];
    const float* W2    = (const float*)d_in[6];
    const float* b2    = (const float*)d_in[7];
    const float* W3    = (const float*)d_in[8];
    const float* b3    = (const float*)d_in[9];
    float* out = (float*)d_out;

    // one-time resource setup (handles only; no device memory)
    static cudaStream_t s2 = []() {
        cudaStream_t s; cudaStreamCreateWithFlags(&s, cudaStreamNonBlocking); return s;
    }();
    static cudaEvent_t evFork = []() {
        cudaEvent_t e; cudaEventCreateWithFlags(&e, cudaEventDisableTiming); return e;
    }();
    static cudaEvent_t evGemm = []() {
        cudaEvent_t e; cudaEventCreateWithFlags(&e, cudaEventDisableTiming); return e;
    }();

    // fork: GEMM on s2, independent of the edge-processing chain
    cudaEventRecord(evFork, 0);
    cudaStreamWaitEvent(s2, evFork, 0);
    gemm_kernel<<<(N_NODES + GM_M - 1) / GM_M, 256, 0, s2>>>(x, W_gcn);
    cudaEventRecord(evGemm, s2);

    // main stream: degree -> dinv -> rowptr -> csr
    zero_detect_kernel<<<NB, 256>>>((const int*)ei);
    count_kernel<<<(N_EDGES + 255) / 256, 256>>>(ei);
    bsum_kernel<<<NB, 256>>>();
    rowptr_kernel<<<NB, 256>>>();
    csr_kernel<<<(N_EDGES + 255) / 256, 256>>>(ei);

    // join: aggregate needs both CSR and H
    cudaStreamWaitEvent(0, evGemm, 0);
    aggregate_kernel<<<(N_NODES + 7) / 8, 256>>>();
    mlp_kernel<<<(N_NODES + 127) / 128, 128>>>(b_gcn, W1, b1, W2, b2, W3, b3, out);
}